// round 4
// baseline (speedup 1.0000x reference)
#include <cuda_runtime.h>
#include <math.h>

#define N 96
#define NN (N*N)            // 9216
#define IN_DIM 64
#define HID 256
#define ZD 64
#define E 1024
#define U 4560
#define NUM_LOGITS 4656
#define ITERS 50

// ---------------- device scratch (no allocations allowed) ----------------
__device__ float g_Anorm[NN];
__device__ float g_T[N*HID];      // gemm outputs (reused for layer1/layer2)
__device__ float g_P[N*HID];      // A_norm @ T (reused)
__device__ float g_H[N*HID];      // post-BN activations (reused)
__device__ float g_gv[HID];
__device__ float g_d1[HID];
__device__ float g_B[NN];         // symmetric sigmoid matrix
__device__ float g_degA[N];
__device__ float g_nd[NN];
__device__ int   g_deg[N];
__device__ int   g_nbr[NN];
__device__ float g_X[NN];
__device__ float g_M[2][NN];
__device__ float g_ss[ITERS+2];

// ---------------- prologue ----------------

// Build A_norm from edge_index; degA + neighbor CSR from adj_gt; reset ss.
__global__ void k_adj(const int* __restrict__ ei, const float* __restrict__ adj) {
    __shared__ float sA[NN];
    __shared__ float sdinv[N];
    int tid = threadIdx.x;
    for (int i = tid; i < NN; i += blockDim.x) sA[i] = 0.f;
    __syncthreads();
    for (int e = tid; e < E; e += blockDim.x) {
        int s = ei[e], d = ei[E + e];
        sA[s * N + d] = 1.f;           // racing writes of identical value: benign
    }
    __syncthreads();
    if (tid < N) sA[tid * (N + 1)] = 1.f;   // A = max(A, I)
    __syncthreads();
    if (tid < N) {
        float sum = 0.f;
        for (int j = 0; j < N; j++) sum += sA[tid * N + j];
        sdinv[tid] = rsqrtf(sum);
    }
    __syncthreads();
    for (int i = tid; i < NN; i += blockDim.x) {
        int r = i / N, c = i % N;
        g_Anorm[i] = sA[i] * sdinv[r] * sdinv[c];
    }
    if (tid < N) {
        float s = 0.f; int cnt = 0;
        for (int j = 0; j < N; j++) {
            float v = adj[tid * N + j];
            s += v;
            if (v > 0.5f) g_nbr[tid * N + cnt++] = j;
        }
        g_degA[tid] = s + 1.f;          // Agt has diag forced to 1
        g_deg[tid]  = cnt;
    }
    if (tid < ITERS + 2) g_ss[tid] = (tid == 0) ? 1.f : 0.f;  // ||X0||_F = 1 exactly
}

// T = x @ W1   (96x64 @ 64x256)
__global__ void k_gemm1(const float* __restrict__ x, const float* __restrict__ W1) {
    __shared__ float sx[IN_DIM];
    int i = blockIdx.x, c = threadIdx.x;
    if (c < IN_DIM) sx[c] = x[i * IN_DIM + c];
    __syncthreads();
    float acc = 0.f;
#pragma unroll
    for (int k = 0; k < IN_DIM; k++) acc += sx[k] * W1[k * HID + c];
    g_T[i * HID + c] = acc;
}

// P = A_norm @ T
__global__ void k_gcn() {
    __shared__ float sa[N];
    int i = blockIdx.x, c = threadIdx.x;
    if (c < N) sa[c] = g_Anorm[i * N + c];
    __syncthreads();
    float acc = 0.f;
#pragma unroll 4
    for (int j = 0; j < N; j++) acc += sa[j] * g_T[j * HID + c];
    g_P[i * HID + c] = acc;
}

// H = relu(BN(P)*gamma + beta); optionally g_gv = mean over rows of H.
// (bias b is dropped: BN exactly cancels per-column additive constants)
__global__ void k_bn(const float* __restrict__ gamma, const float* __restrict__ beta,
                     int compute_gv) {
    int c = threadIdx.x;
    float s = 0.f, q = 0.f;
    for (int i = 0; i < N; i++) { float v = g_P[i * HID + c]; s += v; q += v * v; }
    float m = s * (1.f / N);
    float var = q * (1.f / N) - m * m;
    float inv = rsqrtf(var + 1e-5f) * gamma[c];
    float bb = beta[c];
    float gs = 0.f;
    for (int i = 0; i < N; i++) {
        float h = (g_P[i * HID + c] - m) * inv + bb;
        h = fmaxf(h, 0.f);
        g_H[i * HID + c] = h;
        gs += h;
    }
    if (compute_gv) g_gv[c] = gs * (1.f / N);
}

// T = H @ W2   (96x256 @ 256x256)
__global__ void k_gemm2(const float* __restrict__ W2) {
    __shared__ float sh[HID];
    int i = blockIdx.x, c = threadIdx.x;
    sh[c] = g_H[i * HID + c];
    __syncthreads();
    float acc = 0.f;
#pragma unroll 4
    for (int k = 0; k < HID; k++) acc += sh[k] * W2[k * HID + c];
    g_T[i * HID + c] = acc;
}

// mu/lv/z + first decoder layer: d1 = relu(z @ Wd1 + bd1)
__global__ void k_head(const float* __restrict__ Wmu, const float* __restrict__ bmu,
                       const float* __restrict__ Wlv, const float* __restrict__ blv,
                       const float* __restrict__ Wd1, const float* __restrict__ bd1,
                       const float* __restrict__ eps) {
    __shared__ float sg[HID];
    __shared__ float sz[ZD];
    int t = threadIdx.x;
    sg[t] = g_gv[t];
    __syncthreads();
    if (t < ZD) {
        float mu = bmu[t], lv = blv[t];
        for (int k = 0; k < HID; k++) {
            float g = sg[k];
            mu += g * Wmu[k * ZD + t];
            lv += g * Wlv[k * ZD + t];
        }
        lv = fminf(fmaxf(lv, -4.f), 4.f);
        sz[t] = mu + eps[t] * expf(0.5f * lv);
    }
    __syncthreads();
    float acc = bd1[t];
#pragma unroll
    for (int d = 0; d < ZD; d++) acc += sz[d] * Wd1[d * HID + t];
    g_d1[t] = fmaxf(acc, 0.f);
}

// vec = tanh(d1 @ Wd2 + bd2) scattered directly into symmetric B (diag = 1)
__global__ void k_decB(const float* __restrict__ Wd2, const float* __restrict__ bd2) {
    __shared__ float sd[HID];
    int r = blockIdx.x, c = threadIdx.x;
    for (int k = c; k < HID; k += N) sd[k] = g_d1[k];
    __syncthreads();
    if (c == r) g_B[r * N + r] = 1.f;
    if (c > r) {
        int u = r * (N - 1) - (r * (r - 1)) / 2 + (c - r - 1);
        float acc = bd2[u];
#pragma unroll 4
        for (int k = 0; k < HID; k++) acc += sd[k] * Wd2[k * NUM_LOGITS + u];
        float th = tanhf(acc);
        float sig = 1.f / (1.f + expf(-th));
        g_B[r * N + c] = sig;
        g_B[c * N + r] = sig;
    }
}

// nd, X0, M0.  M0[j,k] = (1/N) * max_{l!=k} B[k,l]  (X0 uniform)
__global__ void k_prep() {
    int i = blockIdx.x, k = threadIdx.x;
    float db = 0.f, mx = 0.f;
#pragma unroll 4
    for (int l = 0; l < N; l++) {
        float b = g_B[k * N + l];
        db += b;
        if (l != k) mx = fmaxf(mx, b);
    }
    g_nd[i * N + k] = 1.f / (fabsf(g_degA[i] - db) + 1.f);
    g_X[i * N + k]  = 1.f / N;
    g_M[0][i * N + k] = mx * (1.f / N);
}

// ---------------- MPM iteration (one kernel per step) ----------------
// Block i owns row i.  Reads M_t rows of its adj_gt neighbors + own X row,
// applies the carried normalization scalar, writes X_{t+1} row, accumulates
// sumsq for the next scale, then computes M_{t+1} row from the fresh X row.
__global__ void k_iter(int t, int last) {
    __shared__ float sx[N];
    __shared__ float red[3];
    int i = blockIdx.x, k = threadIdx.x;
    const float* __restrict__ Min = g_M[t & 1];
    float* __restrict__ Mout = g_M[(t + 1) & 1];
    float scale = rsqrtf(g_ss[t]);

    float acc = g_X[i * N + k] * g_nd[i * N + k];
    int dg = g_deg[i];
    for (int m = 0; m < dg; m++) {
        int j = g_nbr[i * N + m];
        acc += Min[j * N + k];
    }
    acc *= scale;                 // == F(X_t / ||X_t||)  (F positively homogeneous)
    g_X[i * N + k] = acc;
    sx[k] = acc;

    float sq = acc * acc;
#pragma unroll
    for (int o = 16; o > 0; o >>= 1) sq += __shfl_down_sync(0xffffffffu, sq, o);
    if ((k & 31) == 0) red[k >> 5] = sq;
    __syncthreads();
    if (k == 0) atomicAdd(&g_ss[t + 1], red[0] + red[1] + red[2]);

    if (!last) {
        // M[i,k] = max_{l!=k} B[k,l] * x_new[l];  B symmetric -> B[l*N+k] coalesced
        float mx = 0.f;
#pragma unroll 4
        for (int l = 0; l < N; l++) {
            float v = g_B[l * N + k] * sx[l];
            if (l != k) mx = fmaxf(mx, v);
        }
        Mout[i * N + k] = mx;
    }
}

__global__ void k_final(float* __restrict__ out) {
    int idx = blockIdx.x * blockDim.x + threadIdx.x;
    float scale = rsqrtf(g_ss[ITERS]);
    if (idx < NN) out[idx] = g_X[idx] * scale;
}

// ---------------- launch ----------------
extern "C" void kernel_launch(void* const* d_in, const int* in_sizes, int n_in,
                              void* d_out, int out_size) {
    const float* x    = (const float*)d_in[0];
    const int*   ei   = (const int*)  d_in[1];
    const float* adj  = (const float*)d_in[2];
    const float* W1   = (const float*)d_in[3];
    // d_in[4] = b1 (exactly cancelled by BN)
    const float* g1   = (const float*)d_in[5];
    const float* be1  = (const float*)d_in[6];
    const float* W2   = (const float*)d_in[7];
    // d_in[8] = b2 (exactly cancelled by BN)
    const float* g2   = (const float*)d_in[9];
    const float* be2  = (const float*)d_in[10];
    const float* Wmu  = (const float*)d_in[11];
    const float* bmu  = (const float*)d_in[12];
    const float* Wlv  = (const float*)d_in[13];
    const float* blv  = (const float*)d_in[14];
    const float* Wd1  = (const float*)d_in[15];
    const float* bd1  = (const float*)d_in[16];
    const float* Wd2  = (const float*)d_in[17];
    const float* bd2  = (const float*)d_in[18];
    const float* eps  = (const float*)d_in[19];

    k_adj<<<1, 128>>>(ei, adj);
    k_gemm1<<<N, HID>>>(x, W1);
    k_gcn<<<N, HID>>>();
    k_bn<<<1, HID>>>(g1, be1, 0);
    k_gemm2<<<N, HID>>>(W2);
    k_gcn<<<N, HID>>>();
    k_bn<<<1, HID>>>(g2, be2, 1);
    k_head<<<1, HID>>>(Wmu, bmu, Wlv, blv, Wd1, bd1, eps);
    k_decB<<<N, N>>>(Wd2, bd2);
    k_prep<<<N, N>>>();
    for (int t = 0; t < ITERS; t++)
        k_iter<<<N, N>>>(t, (t == ITERS - 1) ? 1 : 0);
    k_final<<<(NN + 255) / 256, 256>>>((float*)d_out);
}

// round 5
// speedup vs baseline: 1.3403x; 1.3403x over previous
#include <cuda_runtime.h>
#include <math.h>

#define N        96
#define NB       96      // blocks
#define NT       96      // threads per block
#define NN       9216
#define IN_DIM   64
#define HID      256
#define ZD       64
#define E        1024
#define NUM_LOGITS 4656
#define ITERS    50

// ---------------- device scratch (no allocations allowed) ----------------
__device__ float g_Anorm[NN];
__device__ float g_T[N * HID];
__device__ float g_P[N * HID];
__device__ float g_H[N * HID];
__device__ float g_gv[HID];
__device__ float g_d1[HID];
__device__ float g_B[NN];
__device__ float g_degA[N];
__device__ int   g_deg[N];
__device__ int   g_nbr[NN];
__device__ float g_M[2][NN];        // cross-block double buffer
__device__ float g_part[NB];        // per-block sum-of-squares partials
__device__ int      g_cnt;          // barrier arrival counter (returns to 0)
__device__ unsigned g_gen;          // barrier generation (monotonic, wrap-safe)

__global__ void __launch_bounds__(NT, 1) fused_graphvae(
    const float* __restrict__ x,   const int* __restrict__ ei,
    const float* __restrict__ adj,
    const float* __restrict__ W1,  const float* __restrict__ g1,  const float* __restrict__ be1,
    const float* __restrict__ W2,  const float* __restrict__ g2,  const float* __restrict__ be2,
    const float* __restrict__ Wmu, const float* __restrict__ bmu,
    const float* __restrict__ Wlv, const float* __restrict__ blv,
    const float* __restrict__ Wd1, const float* __restrict__ bd1,
    const float* __restrict__ Wd2, const float* __restrict__ bd2,
    const float* __restrict__ eps, float* __restrict__ out)
{
    extern __shared__ float dyn[];        // 9216 floats: sA (phase 0) / Bsh (MPM)
    __shared__ float sbuf[HID];           // multi-purpose staging
    __shared__ float sxX[N];              // block-local X row
    __shared__ float snd[N];              // block-local nd row
    __shared__ int   snbr[N];             // neighbor list of this row
    __shared__ float red[4];
    __shared__ unsigned s_gen0;
    __shared__ int   s_deg;

    const int t    = threadIdx.x;         // 0..95
    const int bid  = blockIdx.x;          // 0..95
    const int lane = t & 31, wid = t >> 5;

    if (t == 0) s_gen0 = *(volatile unsigned*)&g_gen;
    __syncthreads();
    unsigned ph = 0;

    // sense-reversal grid barrier: counter self-resets, generation monotonic.
    auto bar = [&]() {
        ph++;
        __syncthreads();
        if (t == 0) {
            __threadfence();
            int old = atomicAdd(&g_cnt, 1);
            if (old == NB - 1) {
                g_cnt = 0;
                __threadfence();
                atomicAdd(&g_gen, 1u);
            } else {
                unsigned target = s_gen0 + ph;
                while ((int)(*(volatile unsigned*)&g_gen - target) < 0) { }
            }
            __threadfence();
        }
        __syncthreads();
    };

    // ---------- P0: adjacency, A_norm, neighbor CSR (block 0 only) ----------
    if (bid == 0) {
        for (int i = t; i < NN; i += NT) dyn[i] = 0.f;
        __syncthreads();
        for (int e = t; e < E; e += NT) {
            int s = ei[e], d = ei[E + e];
            dyn[s * N + d] = 1.f;          // identical-value races: benign
        }
        __syncthreads();
        dyn[t * (N + 1)] = 1.f;            // A = max(A, I)
        __syncthreads();
        {
            float sum = 0.f;
            for (int j = 0; j < N; j++) sum += dyn[t * N + j];
            sbuf[t] = rsqrtf(sum);
        }
        __syncthreads();
        for (int i = t; i < NN; i += NT) {
            int r = i / N, c = i - r * N;
            g_Anorm[i] = dyn[i] * sbuf[r] * sbuf[c];
        }
        {
            float s = 0.f; int cnt = 0;
            for (int j = 0; j < N; j++) {
                float v = adj[t * N + j];
                s += v;
                if (v > 0.5f) g_nbr[t * N + cnt++] = j;
            }
            g_degA[t] = s + 1.f;           // Agt diag forced to 1
            g_deg[t]  = cnt;
        }
    }
    bar();

    // ---------- P1: T = x @ W1 (bias b1 exactly cancelled by BN) ----------
    {
        if (t < IN_DIM) sbuf[t] = x[bid * IN_DIM + t];
        __syncthreads();
        for (int c = t; c < HID; c += NT) {
            float acc = 0.f;
            #pragma unroll
            for (int k = 0; k < IN_DIM; k++) acc += sbuf[k] * W1[k * HID + c];
            g_T[bid * HID + c] = acc;
        }
    }
    bar();

    // ---------- P = A_norm @ T ----------
    auto gcn = [&]() {
        sbuf[t] = g_Anorm[bid * N + t];
        __syncthreads();
        for (int c = t; c < HID; c += NT) {
            float acc = 0.f;
            #pragma unroll 4
            for (int j = 0; j < N; j++) acc += sbuf[j] * g_T[j * HID + c];
            g_P[bid * HID + c] = acc;
        }
    };
    gcn(); bar();

    // ---------- BN + relu, warp-per-column ----------
    auto bn = [&](const float* gamma, const float* beta, int do_gv) {
        int c = bid * 3 + wid;
        if (c < HID) {
            float v0 = g_P[lane * HID + c];
            float v1 = g_P[(lane + 32) * HID + c];
            float v2 = g_P[(lane + 64) * HID + c];
            float s = v0 + v1 + v2;
            float q = v0 * v0 + v1 * v1 + v2 * v2;
            #pragma unroll
            for (int o = 16; o > 0; o >>= 1) {
                s += __shfl_xor_sync(~0u, s, o);
                q += __shfl_xor_sync(~0u, q, o);
            }
            float m   = s * (1.f / N);
            float var = q * (1.f / N) - m * m;
            float inv = rsqrtf(var + 1e-5f) * gamma[c];
            float bb  = beta[c];
            float h0 = fmaxf((v0 - m) * inv + bb, 0.f);
            float h1 = fmaxf((v1 - m) * inv + bb, 0.f);
            float h2 = fmaxf((v2 - m) * inv + bb, 0.f);
            g_H[lane * HID + c] = h0;
            g_H[(lane + 32) * HID + c] = h1;
            g_H[(lane + 64) * HID + c] = h2;
            if (do_gv) {
                float gs = h0 + h1 + h2;
                #pragma unroll
                for (int o = 16; o > 0; o >>= 1) gs += __shfl_xor_sync(~0u, gs, o);
                if (lane == 0) g_gv[c] = gs * (1.f / N);
            }
        }
    };
    bn(g1, be1, 0); bar();

    // ---------- T = H @ W2 ----------
    {
        for (int k = t; k < HID; k += NT) sbuf[k] = g_H[bid * HID + k];
        __syncthreads();
        for (int c = t; c < HID; c += NT) {
            float acc = 0.f;
            #pragma unroll 4
            for (int k = 0; k < HID; k++) acc += sbuf[k] * W2[k * HID + c];
            g_T[bid * HID + c] = acc;
        }
    }
    bar();
    gcn(); bar();
    bn(g2, be2, 1); bar();

    // ---------- head: z, d1 (block 0) ----------
    if (bid == 0) {
        if (t < ZD) {
            float mu = bmu[t], lv = blv[t];
            for (int k = 0; k < HID; k++) {
                float g = g_gv[k];
                mu += g * Wmu[k * ZD + t];
                lv += g * Wlv[k * ZD + t];
            }
            lv = fminf(fmaxf(lv, -4.f), 4.f);
            sbuf[t] = mu + eps[t] * expf(0.5f * lv);
        }
        __syncthreads();
        for (int c = t; c < HID; c += NT) {
            float acc = bd1[c];
            #pragma unroll
            for (int d = 0; d < ZD; d++) acc += sbuf[d] * Wd1[d * HID + c];
            g_d1[c] = fmaxf(acc, 0.f);
        }
    }
    bar();

    // ---------- decoder -> symmetric B (diag = 1) ----------
    {
        for (int k = t; k < HID; k += NT) sbuf[k] = g_d1[k];
        __syncthreads();
        int r = bid, c = t;
        if (c == r) g_B[r * N + r] = 1.f;
        if (c > r) {
            int u = r * (N - 1) - (r * (r - 1)) / 2 + (c - r - 1);
            float acc = bd2[u];
            #pragma unroll 4
            for (int k = 0; k < HID; k++) acc += sbuf[k] * Wd2[k * NUM_LOGITS + u];
            float th  = tanhf(acc);
            float sig = 1.f / (1.f + expf(-th));
            g_B[r * N + c] = sig;
            g_B[c * N + r] = sig;
        }
    }
    bar();

    // ---------- prep: Bsh (diag-zeroed) into shared, nd, X0, M0 ----------
    {
        for (int j = 0; j < N; j++)
            dyn[j * N + t] = (j == t) ? 0.f : g_B[j * N + t];
        float db = 0.f;
        #pragma unroll 4
        for (int l = 0; l < N; l++) db += g_B[t * N + l];
        __syncthreads();
        float mx = 0.f;
        #pragma unroll 4
        for (int l = 0; l < N; l++) mx = fmaxf(mx, dyn[l * N + t]);
        snd[t] = 1.f / (fabsf(g_degA[bid] - db) + 1.f);
        sxX[t] = 1.f / N;                       // ||X0||_F = 1 exactly
        g_M[0][bid * N + t] = mx * (1.f / N);
        snbr[t] = g_nbr[bid * N + t];
        if (t == 0) s_deg = g_deg[bid];
    }
    bar();

    // ---------- 50 MPM iterations, one grid barrier each ----------
    // F is positively homogeneous: carry the exact norm as a scalar, resolved
    // deterministically each iteration from per-block partials (no atomics).
    const int row = bid * N;
    for (int it = 0; it < ITERS; it++) {
        const float* __restrict__ Min  = g_M[it & 1];
        float*       __restrict__ Mout = g_M[(it + 1) & 1];

        float scale;
        if (it == 0) scale = 1.f;
        else {
            float p = g_part[t];                 // t < 96 == NB
            #pragma unroll
            for (int o = 16; o > 0; o >>= 1) p += __shfl_xor_sync(~0u, p, o);
            if (lane == 0) red[wid] = p;
            __syncthreads();
            scale = rsqrtf(red[0] + red[1] + red[2]);
            __syncthreads();
        }

        float acc = sxX[t] * snd[t];
        int dg = s_deg;
        for (int m = 0; m < dg; m++) acc += Min[snbr[m] * N + t];
        acc *= scale;
        sxX[t] = acc;

        float sq = acc * acc;
        #pragma unroll
        for (int o = 16; o > 0; o >>= 1) sq += __shfl_xor_sync(~0u, sq, o);
        if (lane == 0) red[wid] = sq;
        __syncthreads();
        if (t == 0) g_part[bid] = red[0] + red[1] + red[2];

        if (it != ITERS - 1) {
            // M[i,k] = max_{l!=k} B[k,l]*x[l]; B symmetric, diag zeroed in dyn
            float mx = 0.f;
            #pragma unroll 8
            for (int l = 0; l < N; l++) mx = fmaxf(mx, dyn[l * N + t] * sxX[l]);
            Mout[row + t] = mx;
        }
        bar();
    }

    // ---------- final normalize + write ----------
    {
        float p = g_part[t];
        #pragma unroll
        for (int o = 16; o > 0; o >>= 1) p += __shfl_xor_sync(~0u, p, o);
        if (lane == 0) red[wid] = p;
        __syncthreads();
        float os = rsqrtf(red[0] + red[1] + red[2]);
        out[row + t] = sxX[t] * os;
    }
}

// ---------------- launch ----------------
extern "C" void kernel_launch(void* const* d_in, const int* in_sizes, int n_in,
                              void* d_out, int out_size) {
    const float* x   = (const float*)d_in[0];
    const int*   ei  = (const int*)  d_in[1];
    const float* adj = (const float*)d_in[2];
    const float* W1  = (const float*)d_in[3];
    // d_in[4] = b1 (cancelled by BN)
    const float* g1  = (const float*)d_in[5];
    const float* be1 = (const float*)d_in[6];
    const float* W2  = (const float*)d_in[7];
    // d_in[8] = b2 (cancelled by BN)
    const float* g2  = (const float*)d_in[9];
    const float* be2 = (const float*)d_in[10];
    const float* Wmu = (const float*)d_in[11];
    const float* bmu = (const float*)d_in[12];
    const float* Wlv = (const float*)d_in[13];
    const float* blv = (const float*)d_in[14];
    const float* Wd1 = (const float*)d_in[15];
    const float* bd1 = (const float*)d_in[16];
    const float* Wd2 = (const float*)d_in[17];
    const float* bd2 = (const float*)d_in[18];
    const float* eps = (const float*)d_in[19];

    fused_graphvae<<<NB, NT, NN * sizeof(float)>>>(
        x, ei, adj, W1, g1, be1, W2, g2, be2,
        Wmu, bmu, Wlv, blv, Wd1, bd1, Wd2, bd2, eps, (float*)d_out);
}

// round 6
// speedup vs baseline: 1.4259x; 1.0638x over previous
#include <cuda_runtime.h>
#include <math.h>

#define N        96
#define NB       32      // blocks; block b owns rows 3b..3b+2
#define NT       288     // threads per block (9 warps)
#define NN       9216
#define IN_DIM   64
#define HID      256
#define ZD       64
#define E        1024
#define NUM_LOGITS 4656
#define ITERS    50
#define UTRI     4560    // N*(N-1)/2

// ---------------- device scratch (no allocations allowed) ----------------
__device__ float g_Anorm[NN];
__device__ float g_T[N * HID];
__device__ float g_P[N * HID];
__device__ float g_H[N * HID];
__device__ float g_gv[HID];
__device__ float g_d1[HID];
__device__ float g_B[NN];
__device__ float g_degA[N];
__device__ int   g_deg[N];
__device__ int   g_nbr[NN];
__device__ float g_M[2][NN];          // cross-block double buffer
__device__ float g_part[NB];          // per-block sum-of-squares partials
__device__ unsigned g_cnt_arr[32];    // [0] = arrival counter (padded line)
__device__ unsigned g_gen_arr[32];    // [0] = generation      (padded line)

__global__ void __launch_bounds__(NT, 1) fused_graphvae(
    const float* __restrict__ x,   const int* __restrict__ ei,
    const float* __restrict__ adj,
    const float* __restrict__ W1,  const float* __restrict__ g1,  const float* __restrict__ be1,
    const float* __restrict__ W2,  const float* __restrict__ g2,  const float* __restrict__ be2,
    const float* __restrict__ Wmu, const float* __restrict__ bmu,
    const float* __restrict__ Wlv, const float* __restrict__ blv,
    const float* __restrict__ Wd1, const float* __restrict__ bd1,
    const float* __restrict__ Wd2, const float* __restrict__ bd2,
    const float* __restrict__ eps, float* __restrict__ out)
{
    __shared__ float dyn[NN];          // 36 KB: adjacency / staging / B' in MPM
    __shared__ float sX[3 * N];        // block's 3 X rows
    __shared__ float sND[3 * N];       // block's 3 nd rows
    __shared__ int   snbr[3 * N];      // neighbor lists for the 3 rows
    __shared__ int   sdeg[3];
    __shared__ float spart[9 * N];     // [chunk][row][k] partial maxes / temps
    __shared__ float red[16];
    __shared__ float s_scale;
    __shared__ unsigned s_gen0;

    const int t    = threadIdx.x;            // 0..287
    const int bid  = blockIdx.x;             // 0..31
    const int lane = t & 31, wid = t >> 5;
    const int r    = t / 96;                 // row-in-block AND chunk id (0..2)
    const int k    = t - r * 96;             // column 0..95
    const int grow = 3 * bid + r;            // global row

    if (t == 0) s_gen0 = *(volatile unsigned*)&g_gen_arr[0];
    __syncthreads();
    unsigned ph = 0;

    // Grid barrier. NOTE: the gpu-scope __threadfence emits CCTL.IVALL which
    // invalidates this SM's L1D — required so post-barrier reads of g_M /
    // g_part / g_* see other blocks' writes (L1 is not coherent).
    auto bar = [&]() {
        ph++;
        __syncthreads();
        if (t == 0) {
            __threadfence();
            unsigned old = atomicAdd(&g_cnt_arr[0], 1u);
            if (old == NB - 1) {
                g_cnt_arr[0] = 0;
                __threadfence();
                atomicAdd(&g_gen_arr[0], 1u);
            } else {
                unsigned target = s_gen0 + ph;
                while ((int)(*(volatile unsigned*)&g_gen_arr[0] - target) < 0) { }
            }
            __threadfence();
        }
        __syncthreads();
    };

    // ================= Phase A: adjacency (block 0) + gemm1 (blocks 1..31) ==
    if (bid == 0) {
        for (int i = t; i < NN; i += NT) dyn[i] = 0.f;
        __syncthreads();
        for (int e = t; e < E; e += NT) {
            int s = ei[e], d = ei[E + e];
            dyn[s * N + d] = 1.f;                 // identical-value races: benign
        }
        __syncthreads();
        if (t < N) dyn[t * (N + 1)] = 1.f;        // A = max(A, I)
        __syncthreads();
        for (int row = wid; row < N; row += 9) {  // warp-per-row sum: no conflicts
            float s = dyn[row * N + lane] + dyn[row * N + lane + 32]
                    + dyn[row * N + lane + 64];
            #pragma unroll
            for (int o = 16; o > 0; o >>= 1) s += __shfl_xor_sync(~0u, s, o);
            if (lane == 0) spart[row] = rsqrtf(s);
        }
        __syncthreads();
        for (int i = t; i < NN; i += NT) {
            int rr = i / N, cc = i - rr * N;
            g_Anorm[i] = dyn[i] * spart[rr] * spart[cc];
        }
        if (t < N) {
            float s = 0.f; int cnt = 0;
            for (int j = 0; j < N; j++) {
                float v = adj[t * N + j];
                s += v;
                if (v > 0.5f) g_nbr[t * N + cnt++] = j;
            }
            g_degA[t] = s + 1.f;                  // Agt diag forced to 1
            g_deg[t]  = cnt;
        }
    } else {
        // T = x @ W1 (bias b1 exactly cancelled by BN)
        for (int i = t; i < N * IN_DIM; i += NT) dyn[i] = x[i];
        __syncthreads();
        for (int o = (bid - 1) * NT + t; o < N * HID; o += (NB - 1) * NT) {
            int i = o >> 8, c = o & 255;
            float acc = 0.f;
            #pragma unroll
            for (int kk = 0; kk < IN_DIM; kk++)
                acc += dyn[i * IN_DIM + kk] * W1[kk * HID + c];
            g_T[o] = acc;
        }
    }
    bar();

    // ================= P = A_norm @ T (3 rows per block) ==================
    auto gcn = [&]() {
        dyn[t] = g_Anorm[grow * N + k];           // stage 3 A_norm rows
        __syncthreads();
        for (int o = t; o < 3 * HID; o += NT) {
            int rr = o >> 8, c = o & 255;
            float acc = 0.f;
            #pragma unroll 4
            for (int j = 0; j < N; j++) acc += dyn[rr * N + j] * g_T[j * HID + c];
            g_P[(3 * bid + rr) * HID + c] = acc;
        }
    };
    gcn(); bar();

    // ================= BN + relu, warp-per-column =========================
    auto bn = [&](const float* gamma, const float* beta, int do_gv) {
        if (wid < 8) {
            int c = bid * 8 + wid;
            float v0 = g_P[lane * HID + c];
            float v1 = g_P[(lane + 32) * HID + c];
            float v2 = g_P[(lane + 64) * HID + c];
            float s = v0 + v1 + v2;
            float q = v0 * v0 + v1 * v1 + v2 * v2;
            #pragma unroll
            for (int o = 16; o > 0; o >>= 1) {
                s += __shfl_xor_sync(~0u, s, o);
                q += __shfl_xor_sync(~0u, q, o);
            }
            float m   = s * (1.f / N);
            float var = q * (1.f / N) - m * m;
            float inv = rsqrtf(var + 1e-5f) * gamma[c];
            float bb  = beta[c];
            float h0 = fmaxf((v0 - m) * inv + bb, 0.f);
            float h1 = fmaxf((v1 - m) * inv + bb, 0.f);
            float h2 = fmaxf((v2 - m) * inv + bb, 0.f);
            g_H[lane * HID + c] = h0;
            g_H[(lane + 32) * HID + c] = h1;
            g_H[(lane + 64) * HID + c] = h2;
            if (do_gv) {
                float gs = h0 + h1 + h2;
                #pragma unroll
                for (int o = 16; o > 0; o >>= 1) gs += __shfl_xor_sync(~0u, gs, o);
                if (lane == 0) g_gv[c] = gs * (1.f / N);
            }
        }
    };
    bn(g1, be1, 0); bar();

    // ================= T = H @ W2 =========================================
    {
        for (int o = t; o < 3 * HID; o += NT)
            dyn[o] = g_H[(3 * bid + (o >> 8)) * HID + (o & 255)];
        __syncthreads();
        for (int o = t; o < 3 * HID; o += NT) {
            int rr = o >> 8, c = o & 255;
            float acc = 0.f;
            #pragma unroll 4
            for (int kk = 0; kk < HID; kk++)
                acc += dyn[rr * HID + kk] * W2[kk * HID + c];
            g_T[(3 * bid + rr) * HID + c] = acc;
        }
    }
    bar();
    gcn(); bar();
    bn(g2, be2, 1); bar();

    // ================= head: z, d1 (block 0) ==============================
    if (bid == 0) {
        if (t < HID) dyn[t] = g_gv[t];
        __syncthreads();
        if (t < ZD) {
            float mu = bmu[t], lv = blv[t];
            #pragma unroll 4
            for (int kk = 0; kk < HID; kk++) {
                float g = dyn[kk];
                mu += g * Wmu[kk * ZD + t];
                lv += g * Wlv[kk * ZD + t];
            }
            lv = fminf(fmaxf(lv, -4.f), 4.f);
            dyn[HID + t] = mu + eps[t] * expf(0.5f * lv);
        }
        __syncthreads();
        if (t < HID) {
            float acc = bd1[t];
            #pragma unroll
            for (int d = 0; d < ZD; d++) acc += dyn[HID + d] * Wd1[d * HID + t];
            g_d1[t] = fmaxf(acc, 0.f);
        }
    }
    bar();

    // ================= decoder -> symmetric B (diag = 1) ==================
    {
        if (t < HID) dyn[t] = g_d1[t];
        __syncthreads();
        int u = bid * NT + t;                    // one upper-tri entry per thread
        if (u < UTRI) {
            int uu = u, rr = 0, rem = N - 1;
            while (uu >= rem) { uu -= rem; rem--; rr++; }
            int cc = rr + 1 + uu;
            float acc = bd2[u];
            #pragma unroll 4
            for (int kk = 0; kk < HID; kk++)
                acc += dyn[kk] * Wd2[kk * NUM_LOGITS + u];
            float th  = tanhf(acc);
            float sig = 1.f / (1.f + expf(-th));
            g_B[rr * N + cc] = sig;
            g_B[cc * N + rr] = sig;
        }
        if (bid == NB - 1 && t < N) g_B[t * (N + 1)] = 1.f;
    }
    bar();

    // ================= prep: B' (diag-zeroed) in shared, nd, X0, M0 ========
    {
        for (int i = t; i < NN; i += NT) {
            int rr = i / N, cc = i - rr * N;
            dyn[i] = (rr == cc) ? 0.f : g_B[i];
        }
        __syncthreads();
        if (t < N) {                   // column sums (B symmetric): conflict-free
            float db = 1.f, mx = 0.f;
            #pragma unroll 4
            for (int l = 0; l < N; l++) {
                float b = dyn[l * N + t];
                db += b;
                mx = fmaxf(mx, b);
            }
            spart[t] = db;
            float m0 = mx * (1.f / N);           // X0 uniform, ||X0||_F = 1
            g_M[0][(3 * bid + 0) * N + t] = m0;
            g_M[0][(3 * bid + 1) * N + t] = m0;
            g_M[0][(3 * bid + 2) * N + t] = m0;
        }
        __syncthreads();
        sND[t]  = 1.f / (fabsf(g_degA[grow] - spart[k]) + 1.f);
        sX[t]   = 1.f / N;
        snbr[t] = g_nbr[grow * N + k];
        if (t < 3) sdeg[t] = g_deg[3 * bid + t];
        __syncthreads();
    }
    bar();
    const int myDeg = sdeg[r];
    const int* myNbr = &snbr[r * N];

    // ================= 50 MPM iterations, one grid barrier each ============
    // F positively homogeneous: the norm is a carried scalar, resolved
    // deterministically from per-block partials (no atomics).
    for (int it = 0; it < ITERS; it++) {
        const float* __restrict__ Min  = g_M[it & 1];
        float*       __restrict__ Mout = g_M[(it + 1) & 1];

        if (it == 0) { if (t == 0) s_scale = 1.f; }
        else if (wid == 0) {
            float p = g_part[lane];               // NB == 32 partials
            #pragma unroll
            for (int o = 16; o > 0; o >>= 1) p += __shfl_xor_sync(~0u, p, o);
            if (lane == 0) s_scale = rsqrtf(p);
        }

        float acc = sX[t] * sND[t];
        for (int m = 0; m < myDeg; m++) acc += Min[myNbr[m] * N + k];
        __syncthreads();                          // s_scale ready
        acc *= s_scale;
        sX[t] = acc;

        float sq = acc * acc;
        #pragma unroll
        for (int o = 16; o > 0; o >>= 1) sq += __shfl_xor_sync(~0u, sq, o);
        if (lane == 0) red[wid] = sq;
        __syncthreads();                          // also publishes sX
        if (t == 0) {
            float s = 0.f;
            #pragma unroll
            for (int w = 0; w < 9; w++) s += red[w];
            g_part[bid] = s;
        }

        if (it != ITERS - 1) {
            // M[row,k] = max_{l != k} B[k,l] * x_row[l]
            // thread (chunk=r, k): 32 l's, all 3 rows share the B load.
            const int lbase = r * 32;
            float mx0 = 0.f, mx1 = 0.f, mx2 = 0.f;
            #pragma unroll 8
            for (int ll = 0; ll < 32; ll++) {
                float b = dyn[(lbase + ll) * N + k];   // diag zeroed -> l!=k free
                mx0 = fmaxf(mx0, b * sX[lbase + ll]);
                mx1 = fmaxf(mx1, b * sX[96 + lbase + ll]);
                mx2 = fmaxf(mx2, b * sX[192 + lbase + ll]);
            }
            spart[(r * 3 + 0) * N + k] = mx0;
            spart[(r * 3 + 1) * N + k] = mx1;
            spart[(r * 3 + 2) * N + k] = mx2;
            __syncthreads();
            float mm = fmaxf(fmaxf(spart[(0 * 3 + r) * N + k],
                                   spart[(1 * 3 + r) * N + k]),
                                   spart[(2 * 3 + r) * N + k]);
            Mout[grow * N + k] = mm;
        }
        bar();
    }

    // ================= final normalize + write ============================
    {
        if (wid == 0) {
            float p = g_part[lane];
            #pragma unroll
            for (int o = 16; o > 0; o >>= 1) p += __shfl_xor_sync(~0u, p, o);
            if (lane == 0) s_scale = rsqrtf(p);
        }
        __syncthreads();
        out[grow * N + k] = sX[t] * s_scale;
    }
}

// ---------------- launch ----------------
extern "C" void kernel_launch(void* const* d_in, const int* in_sizes, int n_in,
                              void* d_out, int out_size) {
    const float* x   = (const float*)d_in[0];
    const int*   ei  = (const int*)  d_in[1];
    const float* adj = (const float*)d_in[2];
    const float* W1  = (const float*)d_in[3];
    // d_in[4] = b1 (cancelled by BN)
    const float* g1  = (const float*)d_in[5];
    const float* be1 = (const float*)d_in[6];
    const float* W2  = (const float*)d_in[7];
    // d_in[8] = b2 (cancelled by BN)
    const float* g2  = (const float*)d_in[9];
    const float* be2 = (const float*)d_in[10];
    const float* Wmu = (const float*)d_in[11];
    const float* bmu = (const float*)d_in[12];
    const float* Wlv = (const float*)d_in[13];
    const float* blv = (const float*)d_in[14];
    const float* Wd1 = (const float*)d_in[15];
    const float* bd1 = (const float*)d_in[16];
    const float* Wd2 = (const float*)d_in[17];
    const float* bd2 = (const float*)d_in[18];
    const float* eps = (const float*)d_in[19];

    fused_graphvae<<<NB, NT>>>(
        x, ei, adj, W1, g1, be1, W2, g2, be2,
        Wmu, bmu, Wlv, blv, Wd1, bd1, Wd2, bd2, eps, (float*)d_out);
}